// round 2
// baseline (speedup 1.0000x reference)
#include <cuda_runtime.h>
#include <stdint.h>

#define HIDDEN 128
#define NTYPES 28
#define TABLE_ELEMS (NTYPES * HIDDEN)   // 3584 floats = 14336 B

// ---------------------------------------------------------------------------
// Zero-init the output: 64M floats = 16M float4 stores, grid-stride.
// ---------------------------------------------------------------------------
__global__ void zero_out_kernel(float4* __restrict__ out, long long n4) {
    long long i = (long long)blockIdx.x * blockDim.x + threadIdx.x;
    long long stride = (long long)gridDim.x * blockDim.x;
    float4 z = make_float4(0.f, 0.f, 0.f, 0.f);
    for (; i < n4; i += stride) out[i] = z;
}

// ---------------------------------------------------------------------------
// Fused embedding gather + segment scatter-sum.
// One warp per incidence: lane l reduces columns [4l, 4l+4) with a single
// red.global.add.v4.f32 (no-return L2 reduction).
// NOTE: indices are int32 — JAX without enable_x64 downcasts the reference's
// "int64" arrays to int32 on device.
// ---------------------------------------------------------------------------
__global__ void __launch_bounds__(256)
cycle_embed_scatter_kernel(const int* __restrict__ x,
                           const int* __restrict__ atom_row,
                           const int* __restrict__ cyc_row,
                           const float* __restrict__ emb,
                           float* __restrict__ out,
                           int n_inc)
{
    __shared__ float s_emb[TABLE_ELEMS];
    for (int i = threadIdx.x; i < TABLE_ELEMS; i += blockDim.x)
        s_emb[i] = emb[i];
    __syncthreads();

    const int lane   = threadIdx.x & 31;
    int       warp   = (blockIdx.x * blockDim.x + threadIdx.x) >> 5;
    const int nwarps = (gridDim.x * blockDim.x) >> 5;

    for (int e = warp; e < n_inc; e += nwarps) {
        // Broadcast loads: all lanes issue same address -> single L1 request.
        const int atom = __ldg(&atom_row[e]);
        const int cyc  = __ldg(&cyc_row[e]);
        const int t    = __ldg(&x[atom]);

        const float4 v = *reinterpret_cast<const float4*>(&s_emb[t * HIDDEN + lane * 4]);
        float* dst = out + (size_t)cyc * HIDDEN + lane * 4;
        asm volatile("red.global.add.v4.f32 [%0], {%1, %2, %3, %4};"
                     :: "l"(dst), "f"(v.x), "f"(v.y), "f"(v.z), "f"(v.w)
                     : "memory");
    }
}

// ---------------------------------------------------------------------------
// Launch contract
// Inputs (metadata order):
//   d_in[0]: x             int32 [500000]
//   d_in[1]: atom_to_cycle int32 [2, 2000000]  (row 0 = atom idx, row 1 = cycle idx)
//   d_in[2]: emb_weight    fp32  [28, 128]
// Output: fp32 [500000, 128]
// ---------------------------------------------------------------------------
extern "C" void kernel_launch(void* const* d_in, const int* in_sizes, int n_in,
                              void* d_out, int out_size)
{
    const int*   x   = (const int*)d_in[0];
    const int*   a2c = (const int*)d_in[1];
    const float* emb = (const float*)d_in[2];
    float*       out = (float*)d_out;

    const int n_inc = in_sizes[1] / 2;
    const long long out_elems = (long long)out_size;

    // 1) zero the output
    {
        long long n4 = out_elems / 4;
        int threads = 256;
        int blocks = 148 * 16;   // grid-stride
        zero_out_kernel<<<blocks, threads>>>((float4*)out, n4);
    }

    // 2) fused gather + scatter-sum
    {
        int threads = 256;              // 8 warps/block
        int blocks  = 148 * 16;         // 2368 blocks -> 18944 warps, ~106 inc/warp
        cycle_embed_scatter_kernel<<<blocks, threads>>>(
            x, a2c /*row 0*/, a2c + n_inc /*row 1*/, emb, out, n_inc);
    }
}

// round 3
// speedup vs baseline: 2.5299x; 2.5299x over previous
#include <cuda_runtime.h>

#define HIDDEN 128
#define NTYPES 28
#define MAX_CYCLES 500000
#define MAX_INC    2000000

#define SCAN_THREADS 256
#define SCAN_ITEMS   8
#define SCAN_CHUNK   (SCAN_THREADS * SCAN_ITEMS)          // 2048
#define MAX_NBLK     ((MAX_CYCLES + SCAN_CHUNK - 1) / SCAN_CHUNK)  // 245

// ------- static scratch (allocation-free, lives in device globals) --------
__device__ int           g_counts[MAX_CYCLES];   // per-cycle incidence count
__device__ int           g_offsets[MAX_CYCLES];  // exclusive prefix (bucket start)
__device__ int           g_cursor[MAX_CYCLES];   // running cursor; == bucket end after scatter
__device__ int           g_bsum[MAX_NBLK];       // per-block sums for scan
__device__ unsigned char g_types[MAX_INC];       // cycle-sorted atom types (<28 fits u8)

// ---------------------------------------------------------------------------
__global__ void k_zero_counts(int n) {
    int i = blockIdx.x * blockDim.x + threadIdx.x;
    int stride = gridDim.x * blockDim.x;
    for (; i < n; i += stride) g_counts[i] = 0;
}

__global__ void k_hist(const int* __restrict__ cyc_row, int n) {
    int i = blockIdx.x * blockDim.x + threadIdx.x;
    int stride = gridDim.x * blockDim.x;
    for (; i < n; i += stride)
        atomicAdd(&g_counts[__ldg(&cyc_row[i])], 1);
}

__global__ void k_block_reduce(int n) {
    __shared__ int s[SCAN_THREADS];
    int b = blockIdx.x, tid = threadIdx.x;
    int sum = 0;
#pragma unroll
    for (int k = 0; k < SCAN_ITEMS; k++) {
        int idx = b * SCAN_CHUNK + tid * SCAN_ITEMS + k;
        if (idx < n) sum += g_counts[idx];
    }
    s[tid] = sum; __syncthreads();
    for (int d = SCAN_THREADS / 2; d > 0; d >>= 1) {
        if (tid < d) s[tid] += s[tid + d];
        __syncthreads();
    }
    if (tid == 0) g_bsum[b] = s[0];
}

__global__ void k_scan_bsums(int nblk) {
    if (threadIdx.x == 0) {
        int run = 0;
        for (int i = 0; i < nblk; i++) { int v = g_bsum[i]; g_bsum[i] = run; run += v; }
    }
}

__global__ void k_scan_block(int n) {
    __shared__ int s[SCAN_THREADS];
    int b = blockIdx.x, tid = threadIdx.x;
    int items[SCAN_ITEMS];
    int local = 0;
#pragma unroll
    for (int k = 0; k < SCAN_ITEMS; k++) {
        int idx = b * SCAN_CHUNK + tid * SCAN_ITEMS + k;
        items[k] = (idx < n) ? g_counts[idx] : 0;
        local += items[k];
    }
    s[tid] = local; __syncthreads();
    // Hillis-Steele inclusive scan over thread sums
    for (int d = 1; d < SCAN_THREADS; d <<= 1) {
        int v = (tid >= d) ? s[tid - d] : 0;
        __syncthreads();
        s[tid] += v;
        __syncthreads();
    }
    int run = g_bsum[b] + s[tid] - local;   // exclusive prefix for this thread's first item
#pragma unroll
    for (int k = 0; k < SCAN_ITEMS; k++) {
        int idx = b * SCAN_CHUNK + tid * SCAN_ITEMS + k;
        if (idx < n) {
            g_offsets[idx] = run;
            g_cursor[idx]  = run;
            run += items[k];
        }
    }
}

__global__ void k_scatter(const int* __restrict__ x,
                          const int* __restrict__ atom_row,
                          const int* __restrict__ cyc_row, int n) {
    int i = blockIdx.x * blockDim.x + threadIdx.x;
    int stride = gridDim.x * blockDim.x;
    for (; i < n; i += stride) {
        int atom = __ldg(&atom_row[i]);
        int cyc  = __ldg(&cyc_row[i]);
        int t    = __ldg(&x[atom]);
        int pos  = atomicAdd(&g_cursor[cyc], 1);
        g_types[pos] = (unsigned char)t;
    }
}

// One warp per cycle: sum its bucket's embedding rows from smem, one coalesced
// 512 B float4 store. Writes every row exactly once (no zero-init needed).
__global__ void __launch_bounds__(256)
k_final(const float* __restrict__ emb, float* __restrict__ out, int ncyc) {
    __shared__ float4 s_emb[NTYPES * 32];
    for (int i = threadIdx.x; i < NTYPES * 32; i += blockDim.x)
        s_emb[i] = reinterpret_cast<const float4*>(emb)[i];
    __syncthreads();

    const int lane = threadIdx.x & 31;
    int warp       = (blockIdx.x * blockDim.x + threadIdx.x) >> 5;
    const int nw   = (gridDim.x * blockDim.x) >> 5;

    for (int c = warp; c < ncyc; c += nw) {
        int start = __ldg(&g_offsets[c]);
        int end   = __ldg(&g_cursor[c]);        // bucket end after scatter
        float4 acc = make_float4(0.f, 0.f, 0.f, 0.f);
        for (int i = start; i < end; i++) {
            int t = g_types[i];                  // lane-broadcast load
            float4 v = s_emb[t * 32 + lane];
            acc.x += v.x; acc.y += v.y; acc.z += v.z; acc.w += v.w;
        }
        reinterpret_cast<float4*>(out)[(size_t)c * 32 + lane] = acc;
    }
}

// ---------------------------------------------------------------------------
// Inputs (metadata order):
//   d_in[0]: x             int32 [500000]
//   d_in[1]: atom_to_cycle int32 [2, 2000000]  (row 0 = atom idx, row 1 = cycle idx)
//   d_in[2]: emb_weight    fp32  [28, 128]
// Output: fp32 [500000, 128]
// ---------------------------------------------------------------------------
extern "C" void kernel_launch(void* const* d_in, const int* in_sizes, int n_in,
                              void* d_out, int out_size)
{
    const int*   x   = (const int*)d_in[0];
    const int*   a2c = (const int*)d_in[1];
    const float* emb = (const float*)d_in[2];
    float*       out = (float*)d_out;

    const int n_inc = in_sizes[1] / 2;
    const int ncyc  = out_size / HIDDEN;
    const int nblk  = (ncyc + SCAN_CHUNK - 1) / SCAN_CHUNK;

    // 1) zero per-cycle counters (2 MB, L2)
    k_zero_counts<<<(ncyc + 255) / 256, 256>>>(ncyc);
    // 2) histogram of cycle ids (L2-resident atomics)
    k_hist<<<2368, 256>>>(a2c + n_inc, n_inc);
    // 3-5) exclusive scan -> g_offsets, cursor copy -> g_cursor
    k_block_reduce<<<nblk, SCAN_THREADS>>>(ncyc);
    k_scan_bsums<<<1, 32>>>(nblk);
    k_scan_block<<<nblk, SCAN_THREADS>>>(ncyc);
    // 6) counting-sort scatter of atom types by cycle (L2-resident)
    k_scatter<<<2368, 256>>>(x, a2c, a2c + n_inc, n_inc);
    // 7) per-cycle sum + single coalesced store of each output row
    k_final<<<4736, 256>>>(emb, out, ncyc);
}

// round 4
// speedup vs baseline: 3.0502x; 1.2057x over previous
#include <cuda_runtime.h>

#define HIDDEN 128
#define NTYPES 28
#define MAX_CYCLES 500000
#define MAX_INC    2000000
#define CAP        32              // fixed bucket capacity (Poisson(4) tail ~1e-19)
#define OVF_MAX    8192

// ------- static scratch (allocation-free device globals) --------
__device__ int           g_count[MAX_CYCLES];            // per-cycle fill count
__device__ unsigned char g_types[MAX_CYCLES * CAP];      // 16 MB, L2-resident
__device__ int           g_ovf_n;
__device__ int           g_ovf_cyc[OVF_MAX];
__device__ unsigned char g_ovf_type[OVF_MAX];

// ---------------------------------------------------------------------------
__global__ void k_zero(int ncyc) {
    int i = blockIdx.x * blockDim.x + threadIdx.x;
    int stride = gridDim.x * blockDim.x;
    if (i == 0) g_ovf_n = 0;
    for (; i < ncyc; i += stride) g_count[i] = 0;
}

// Direct-slot scatter: pos = count[cyc]++ ; types[cyc*CAP+pos] = x[atom].
// int4-vectorized index reads (each thread handles 4 incidences).
__global__ void __launch_bounds__(256)
k_scatter(const int* __restrict__ x,
          const int* __restrict__ atom_row,
          const int* __restrict__ cyc_row, int n)
{
    int n4 = n >> 2;
    int i = blockIdx.x * blockDim.x + threadIdx.x;
    int stride = gridDim.x * blockDim.x;
    const int4* a4 = reinterpret_cast<const int4*>(atom_row);
    const int4* c4 = reinterpret_cast<const int4*>(cyc_row);

    for (; i < n4; i += stride) {
        int4 a = __ldg(&a4[i]);
        int4 c = __ldg(&c4[i]);
        int atoms[4] = {a.x, a.y, a.z, a.w};
        int cycs[4]  = {c.x, c.y, c.z, c.w};
#pragma unroll
        for (int k = 0; k < 4; k++) {
            int t   = __ldg(&x[atoms[k]]);
            int cyc = cycs[k];
            int pos = atomicAdd(&g_count[cyc], 1);
            if (pos < CAP) {
                g_types[(size_t)cyc * CAP + pos] = (unsigned char)t;
            } else {
                int o = atomicAdd(&g_ovf_n, 1);
                if (o < OVF_MAX) { g_ovf_cyc[o] = cyc; g_ovf_type[o] = (unsigned char)t; }
            }
        }
    }
    // tail (n % 4) — n is divisible by 4 here (2M), but keep it correct:
    int tail_start = n4 << 2;
    for (int j = tail_start + blockIdx.x * blockDim.x + threadIdx.x; j < n;
         j += stride) {
        int t   = __ldg(&x[__ldg(&atom_row[j])]);
        int cyc = __ldg(&cyc_row[j]);
        int pos = atomicAdd(&g_count[cyc], 1);
        if (pos < CAP) g_types[(size_t)cyc * CAP + pos] = (unsigned char)t;
        else {
            int o = atomicAdd(&g_ovf_n, 1);
            if (o < OVF_MAX) { g_ovf_cyc[o] = cyc; g_ovf_type[o] = (unsigned char)t; }
        }
    }
}

// One warp per cycle: sum bucket rows from smem embedding table,
// single coalesced 512 B float4 store. Every row written exactly once.
__global__ void __launch_bounds__(256)
k_final(const float* __restrict__ emb, float* __restrict__ out, int ncyc) {
    __shared__ float4 s_emb[NTYPES * 32];
    for (int i = threadIdx.x; i < NTYPES * 32; i += blockDim.x)
        s_emb[i] = reinterpret_cast<const float4*>(emb)[i];
    __syncthreads();

    const int lane = threadIdx.x & 31;
    int warp       = (blockIdx.x * blockDim.x + threadIdx.x) >> 5;
    const int nw   = (gridDim.x * blockDim.x) >> 5;

    for (int c = warp; c < ncyc; c += nw) {
        int cnt = __ldg(&g_count[c]);
        if (cnt > CAP) cnt = CAP;              // overflow handled by fixup
        const unsigned char* bucket = &g_types[(size_t)c * CAP];
        float4 acc = make_float4(0.f, 0.f, 0.f, 0.f);
        for (int i = 0; i < cnt; i++) {
            int t = __ldg(&bucket[i]);          // lane-broadcast L1 load
            float4 v = s_emb[t * 32 + lane];
            acc.x += v.x; acc.y += v.y; acc.z += v.z; acc.w += v.w;
        }
        reinterpret_cast<float4*>(out)[(size_t)c * 32 + lane] = acc;
    }
}

// Rarely-taken fixup: atomically add overflow incidences onto finished rows.
__global__ void k_ovf_fixup(const float* __restrict__ emb, float* __restrict__ out) {
    int n = g_ovf_n;
    if (n > OVF_MAX) n = OVF_MAX;
    // one warp per overflow entry, 4 floats per lane
    int lane = threadIdx.x & 31;
    int warp = (blockIdx.x * blockDim.x + threadIdx.x) >> 5;
    int nw   = (gridDim.x * blockDim.x) >> 5;
    for (int e = warp; e < n; e += nw) {
        int cyc = g_ovf_cyc[e];
        int t   = g_ovf_type[e];
#pragma unroll
        for (int k = 0; k < 4; k++)
            atomicAdd(&out[(size_t)cyc * HIDDEN + lane * 4 + k],
                      emb[t * HIDDEN + lane * 4 + k]);
    }
}

// ---------------------------------------------------------------------------
// Inputs (metadata order):
//   d_in[0]: x             int32 [500000]
//   d_in[1]: atom_to_cycle int32 [2, 2000000]  (row 0 = atom idx, row 1 = cycle idx)
//   d_in[2]: emb_weight    fp32  [28, 128]
// Output: fp32 [500000, 128]
// ---------------------------------------------------------------------------
extern "C" void kernel_launch(void* const* d_in, const int* in_sizes, int n_in,
                              void* d_out, int out_size)
{
    const int*   x   = (const int*)d_in[0];
    const int*   a2c = (const int*)d_in[1];
    const float* emb = (const float*)d_in[2];
    float*       out = (float*)d_out;

    const int n_inc = in_sizes[1] / 2;
    const int ncyc  = out_size / HIDDEN;

    k_zero<<<(ncyc + 511) / 512, 512>>>(ncyc);
    k_scatter<<<1184, 256>>>(x, a2c, a2c + n_inc, n_inc);
    k_final<<<4736, 256>>>(emb, out, ncyc);
    k_ovf_fixup<<<32, 256>>>(emb, out);
}